// round 3
// baseline (speedup 1.0000x reference)
#include <cuda_runtime.h>
#include <cstdint>
#include <math.h>
#include <cub/cub.cuh>

// ---------------------------------------------------------------------------
// MaskPath: faithful CUDA reimplementation of the JAX reference, assuming
// jax_threefry_partitionable=True (default since jax 0.5):
//   split(key, n)[i]        = threefry2x32(key, x0=0, x1=i)  (lanes -> child key)
//   random_bits(key,32)[i]  = y0 ^ y1 of threefry2x32(key, 0, i)
// Pipeline:
//   - lexicographic edge sort via packed 40-bit keys (row<<20|col), cub radix
//   - CSR rowptr via binary search on sorted keys
//   - permutation: 2 rounds stable sort by random bits (jax _shuffle @ 1e6)
//   - 3-step random walk with jax.random.uniform bits
//   - edge mask + stable compaction
// Output (float32, 5*E): remaining[2,E], masked[2,E], edge_mask[E] (1.0/0.0)
// ---------------------------------------------------------------------------

#define EMAX 16000000
#define NNODES 1000000
static const int TPB = 256;

__device__ unsigned long long g_keys_a[EMAX];
__device__ unsigned long long g_keys_b[EMAX];
__device__ unsigned char      g_temp[268435456];   // cub temp (256 MB)
__device__ unsigned int       g_rowptr[NNODES + 1];
__device__ unsigned int       g_pk_a[NNODES];
__device__ unsigned int       g_pk_b[NNODES];
__device__ unsigned int       g_pv_a[NNODES];
__device__ unsigned int       g_pv_b[NNODES];
__device__ int                g_hit[NNODES + 1];
__device__ int                g_hsum[NNODES + 1];

// ---------------- threefry2x32 (exactly as in jax/_src/prng.py) ------------
__host__ __device__ __forceinline__
void tf2x32(uint32_t k0, uint32_t k1, uint32_t x0, uint32_t x1,
            uint32_t& o0, uint32_t& o1) {
    uint32_t ks2 = k0 ^ k1 ^ 0x1BD11BDAu;
    x0 += k0; x1 += k1;
#define TF_R(r) { x0 += x1; x1 = (x1 << (r)) | (x1 >> (32 - (r))); x1 ^= x0; }
    TF_R(13) TF_R(15) TF_R(26) TF_R(6)   x0 += k1;  x1 += ks2 + 1u;
    TF_R(17) TF_R(29) TF_R(16) TF_R(24)  x0 += ks2; x1 += k0  + 2u;
    TF_R(13) TF_R(15) TF_R(26) TF_R(6)   x0 += k0;  x1 += k1  + 3u;
    TF_R(17) TF_R(29) TF_R(16) TF_R(24)  x0 += k1;  x1 += ks2 + 4u;
    TF_R(13) TF_R(15) TF_R(26) TF_R(6)   x0 += ks2; x1 += k0  + 5u;
#undef TF_R
    o0 = x0; o1 = x1;
}

// partitionable random_bits, 32-bit, index i (< 2^32): xor of the two lanes
// of threefry2x32(key, hi32(i)=0, lo32(i)=i)
__device__ __forceinline__
uint32_t jax_bits_part(uint2 k, uint32_t i) {
    uint32_t y0, y1;
    tf2x32(k.x, k.y, 0u, i, y0, y1);
    return y0 ^ y1;
}

// partitionable split: child i = both lanes of threefry2x32(key, 0, i)
static inline uint2 h_split(uint2 k, uint32_t i) {
    uint32_t y0, y1;
    tf2x32(k.x, k.y, 0u, i, y0, y1);
    return make_uint2(y0, y1);
}

// ------------------------------- kernels -----------------------------------
__global__ void k_pack(const int* __restrict__ ei, int E,
                       unsigned long long* __restrict__ keys) {
    int i = blockIdx.x * blockDim.x + threadIdx.x;
    if (i >= E) return;
    unsigned long long r = (unsigned long long)(unsigned)ei[i];
    unsigned long long c = (unsigned long long)(unsigned)ei[(size_t)E + i];
    keys[i] = (r << 20) | c;
}

__global__ void k_rowptr(const unsigned long long* __restrict__ keys, int E,
                         unsigned int N, unsigned int* __restrict__ rowptr) {
    unsigned v = blockIdx.x * blockDim.x + threadIdx.x;
    if (v > N) return;
    unsigned long long target = (unsigned long long)v << 20;
    int lo = 0, hi = E;
    while (lo < hi) {
        int mid = (lo + hi) >> 1;
        if (keys[mid] < target) lo = mid + 1; else hi = mid;
    }
    rowptr[v] = (unsigned)lo;
}

__global__ void k_permbits(unsigned int* __restrict__ out_keys,
                           unsigned int* __restrict__ vals_init,
                           int n, uint2 key) {
    int i = blockIdx.x * blockDim.x + threadIdx.x;
    if (i >= n) return;
    out_keys[i] = jax_bits_part(key, (uint32_t)i);
    if (vals_init) vals_init[i] = (unsigned)i;
}

__global__ void k_zero(int* __restrict__ a, int n) {
    int i = blockIdx.x * blockDim.x + threadIdx.x;
    if (i < n) a[i] = 0;
}

__global__ void k_walk(const unsigned int* __restrict__ start,
                       const unsigned int* __restrict__ rowptr,
                       const unsigned long long* __restrict__ keys,
                       int* __restrict__ hit,
                       uint2 kt0, uint2 kt1, uint2 kt2, int S) {
    int i = blockIdx.x * blockDim.x + threadIdx.x;
    if (i >= S) return;
    uint2 kt[3] = { kt0, kt1, kt2 };
    unsigned cur = start[i];
    bool active = true;
#pragma unroll
    for (int t = 0; t < 3; t++) {
        unsigned rp = rowptr[cur];
        unsigned d  = rowptr[cur + 1] - rp;
        bool act = active && (d > 0);
        if (act) {
            hit[cur] = 1;                               // e_id = current node
            uint32_t b = jax_bits_part(kt[t], (uint32_t)i);
            float u = __uint_as_float((b >> 9) | 0x3f800000u) - 1.0f;
            int off = (int)floorf(u * (float)d);
            int dm1 = (int)d - 1;
            off = off > dm1 ? dm1 : off;
            off = off < 0 ? 0 : off;
            cur = (unsigned)(keys[rp + (unsigned)off] & 0xFFFFFu);
        }
        active = act;
    }
}

__global__ void k_scatter_low(const unsigned long long* __restrict__ keys,
                              const int* __restrict__ hit,
                              const int* __restrict__ hsum,
                              float* __restrict__ rem0, float* __restrict__ rem1,
                              float* __restrict__ msk0, float* __restrict__ msk1,
                              float* __restrict__ maskv, int N) {
    int i = blockIdx.x * blockDim.x + threadIdx.x;
    if (i >= N) return;
    unsigned long long k = keys[i];
    float r = (float)(int)(k >> 20), c = (float)(int)(k & 0xFFFFFu);
    int hs = hsum[i];
    if (hit[i]) {
        msk0[hs] = r; msk1[hs] = c; maskv[i] = 0.0f;
    } else {
        int kp = i - hs;
        rem0[kp] = r; rem1[kp] = c; maskv[i] = 1.0f;
    }
}

__global__ void k_scatter_high(const unsigned long long* __restrict__ keys,
                               const int* __restrict__ Mp,
                               float* __restrict__ rem0, float* __restrict__ rem1,
                               float* __restrict__ maskv, int N, int E) {
    int idx = blockIdx.x * blockDim.x + threadIdx.x;
    int i = N + idx;
    if (i >= E) return;
    int M = __ldg(Mp);
    unsigned long long k = keys[i];
    int kp = i - M;
    rem0[kp] = (float)(int)(k >> 20);
    rem1[kp] = (float)(int)(k & 0xFFFFFu);
    maskv[i] = 1.0f;
}

__global__ void k_fill_rem(const int* __restrict__ Mp,
                           float* __restrict__ rem0, float* __restrict__ rem1,
                           int E, int N) {
    int idx = blockIdx.x * blockDim.x + threadIdx.x;
    if (idx >= N) return;
    int M = __ldg(Mp);
    if (idx < M) {
        int j = E - M + idx;
        rem0[j] = -1.0f; rem1[j] = -1.0f;
    }
}

__global__ void k_fill_msk(const int* __restrict__ Mp,
                           float* __restrict__ msk0, float* __restrict__ msk1,
                           int E) {
    int i = blockIdx.x * blockDim.x + threadIdx.x;
    if (i >= E) return;
    int M = __ldg(Mp);
    if (i >= M) { msk0[i] = -1.0f; msk1[i] = -1.0f; }
}

// ------------------------------- launcher ----------------------------------
extern "C" void kernel_launch(void* const* d_in, const int* in_sizes, int n_in,
                              void* d_out, int out_size) {
    (void)n_in; (void)out_size;
    const int* ei = (const int*)d_in[0];
    const int E = in_sizes[0] / 2;
    const int N = NNODES;

    float* out = (float*)d_out;
    float* rem0 = out;
    float* rem1 = out + (size_t)E;
    float* msk0 = out + 2 * (size_t)E;
    float* msk1 = out + 3 * (size_t)E;
    float* maskv = out + 4 * (size_t)E;

    void *pa, *pb, *pt, *prp, *ppka, *ppkb, *ppva, *ppvb, *phit, *phsum;
    cudaGetSymbolAddress(&pa, g_keys_a);
    cudaGetSymbolAddress(&pb, g_keys_b);
    cudaGetSymbolAddress(&pt, g_temp);
    cudaGetSymbolAddress(&prp, g_rowptr);
    cudaGetSymbolAddress(&ppka, g_pk_a);
    cudaGetSymbolAddress(&ppkb, g_pk_b);
    cudaGetSymbolAddress(&ppva, g_pv_a);
    cudaGetSymbolAddress(&ppvb, g_pv_b);
    cudaGetSymbolAddress(&phit, g_hit);
    cudaGetSymbolAddress(&phsum, g_hsum);
    unsigned long long* ka = (unsigned long long*)pa;
    unsigned long long* kb = (unsigned long long*)pb;
    unsigned char* tmp = (unsigned char*)pt;
    unsigned int* rowptr = (unsigned int*)prp;
    unsigned int* pk_a = (unsigned int*)ppka;
    unsigned int* pk_b = (unsigned int*)ppkb;
    unsigned int* pv_a = (unsigned int*)ppva;
    unsigned int* pv_b = (unsigned int*)ppvb;
    int* hit = (int*)phit;
    int* hsum = (int*)phsum;

    // ---- host-side jax key derivations (key(42)), partitionable semantics ----
    uint2 key42 = make_uint2(0u, 42u);
    uint2 kperm = h_split(key42, 0u);   // split(key42)[0]
    uint2 kwalk = h_split(key42, 1u);   // split(key42)[1]
    // _shuffle round 1: key1, sub1 = split(kperm)
    uint2 key1 = h_split(kperm, 0u);
    uint2 sub1 = h_split(kperm, 1u);
    // _shuffle round 2: sub2 = split(key1)[1]
    uint2 sub2 = h_split(key1, 1u);
    // walk keys: split(kwalk, 3)
    uint2 kt0 = h_split(kwalk, 0u);
    uint2 kt1 = h_split(kwalk, 1u);
    uint2 kt2 = h_split(kwalk, 2u);

    const int S = (int)llround((double)N * 0.7);   // 700000

    cudaStream_t st = 0;

    // 1) pack + sort edges by (row, col)
    k_pack<<<(E + TPB - 1) / TPB, TPB, 0, st>>>(ei, E, ka);
    size_t tb1 = 0;
    cub::DeviceRadixSort::SortKeys(nullptr, tb1, ka, kb, E, 0, 40, st);
    cub::DeviceRadixSort::SortKeys(tmp, tb1, ka, kb, E, 0, 40, st);

    // 2) rowptr via binary search
    k_rowptr<<<(N + 1 + TPB - 1) / TPB, TPB, 0, st>>>(kb, E, (unsigned)N, rowptr);

    // 3) jax permutation: 2 stable sort-by-bits rounds
    k_permbits<<<(N + TPB - 1) / TPB, TPB, 0, st>>>(pk_a, pv_a, N, sub1);
    size_t tb2 = 0;
    cub::DeviceRadixSort::SortPairs(nullptr, tb2, pk_a, pk_b, pv_a, pv_b, N, 0, 32, st);
    cub::DeviceRadixSort::SortPairs(tmp, tb2, pk_a, pk_b, pv_a, pv_b, N, 0, 32, st);
    k_permbits<<<(N + TPB - 1) / TPB, TPB, 0, st>>>(pk_a, (unsigned int*)nullptr, N, sub2);
    size_t tb3 = 0;
    cub::DeviceRadixSort::SortPairs(nullptr, tb3, pk_a, pk_b, pv_b, pv_a, N, 0, 32, st);
    cub::DeviceRadixSort::SortPairs(tmp, tb3, pk_a, pk_b, pv_b, pv_a, N, 0, 32, st);

    // 4) random walks -> hit flags
    k_zero<<<(N + 1 + TPB - 1) / TPB, TPB, 0, st>>>(hit, N + 1);
    k_walk<<<(S + TPB - 1) / TPB, TPB, 0, st>>>(pv_a, rowptr, kb, hit,
                                                kt0, kt1, kt2, S);

    // 5) prefix sum of hits (hsum[N] = total masked M)
    size_t tb4 = 0;
    cub::DeviceScan::ExclusiveSum(nullptr, tb4, hit, hsum, N + 1, st);
    cub::DeviceScan::ExclusiveSum(tmp, tb4, hit, hsum, N + 1, st);

    // 6) compaction + mask output
    k_scatter_low<<<(N + TPB - 1) / TPB, TPB, 0, st>>>(kb, hit, hsum,
                                                       rem0, rem1, msk0, msk1,
                                                       maskv, N);
    k_scatter_high<<<(E - N + TPB - 1) / TPB, TPB, 0, st>>>(kb, hsum + N,
                                                            rem0, rem1, maskv,
                                                            N, E);
    k_fill_rem<<<(N + TPB - 1) / TPB, TPB, 0, st>>>(hsum + N, rem0, rem1, E, N);
    k_fill_msk<<<(E + TPB - 1) / TPB, TPB, 0, st>>>(hsum + N, msk0, msk1, E);
}